// round 3
// baseline (speedup 1.0000x reference)
#include <cuda_runtime.h>
#include <cuda_bf16.h>

// Problem constants
#define B_  16
#define C_  256
#define HIDE_ 128
#define HW_ 16384          // 128*128 elements per (b,c) plane
#define HW4_ 4096          // HW_/4 float4 per plane
#define PLANES_ (B_*C_)    // 4096

// Scratch (no cudaMalloc allowed) — tiny
__device__ float g_y0[PLANES_];    // pooled means (B, C)
__device__ float g_gate[PLANES_];  // sigmoid gate (B, C)

// ---------------------------------------------------------------------------
// Kernel 1: global average pool. One CTA per (b,c) plane, 256 threads,
// float4 vectorized, warp shuffle + smem block reduce.
// ---------------------------------------------------------------------------
__global__ __launch_bounds__(256) void k_reduce(const float* __restrict__ x) {
    const int plane = blockIdx.x;
    const float4* __restrict__ p =
        reinterpret_cast<const float4*>(x + (size_t)plane * HW_);

    float sum = 0.f;
#pragma unroll 4
    for (int i = threadIdx.x; i < HW4_; i += 256) {
        float4 v = p[i];
        sum += (v.x + v.y) + (v.z + v.w);
    }
#pragma unroll
    for (int o = 16; o; o >>= 1)
        sum += __shfl_xor_sync(0xffffffffu, sum, o);

    __shared__ float wsum[8];
    if ((threadIdx.x & 31) == 0) wsum[threadIdx.x >> 5] = sum;
    __syncthreads();
    if (threadIdx.x == 0) {
        float t = 0.f;
#pragma unroll
        for (int i = 0; i < 8; i++) t += wsum[i];
        g_y0[plane] = t * (1.f / (float)HW_);
    }
}

// ---------------------------------------------------------------------------
// Kernel 2: the whole tiny MLP chain for all batches. 1 CTA, 128 threads
// (thread j owns HIDE lane j). Negligible runtime.
//   y1 = y0 @ w1^T              (B,HIDE)
//   s  = softmax(w2*y1)         (B,HIDE)
//   y2 = y1*s + y1 @ A2
//   y3 = relu(w3*y2)
//   gate = sigmoid(y3 @ w4^T)   (B,C)
// ---------------------------------------------------------------------------
__global__ __launch_bounds__(128) void k_gate(const float* __restrict__ w1,
                                              const float* __restrict__ w2,
                                              const float* __restrict__ w3,
                                              const float* __restrict__ w4,
                                              const float* __restrict__ A2) {
    __shared__ float sy0[C_];
    __shared__ float sy1[HIDE_];
    __shared__ float sy3[HIDE_];
    __shared__ float wred[4];

    const int j = threadIdx.x;            // 0..127
    const float W2 = w2[0];
    const float W3 = w3[0];

    for (int b = 0; b < B_; b++) {
        // load pooled vector for this batch
        sy0[j]        = g_y0[b * C_ + j];
        sy0[j + 128]  = g_y0[b * C_ + 128 + j];
        __syncthreads();

        // y1[j] = sum_c y0[c] * w1[j,c]
        float acc = 0.f;
        const float* __restrict__ w1r = w1 + j * C_;
#pragma unroll 8
        for (int c = 0; c < C_; c++) acc = fmaf(sy0[c], w1r[c], acc);
        const float y1 = acc;
        sy1[j] = y1;

        // softmax over the 128 lanes of w2*y1
        const float t = W2 * y1;
        float m = t;
#pragma unroll
        for (int o = 16; o; o >>= 1)
            m = fmaxf(m, __shfl_xor_sync(0xffffffffu, m, o));
        if ((j & 31) == 0) wred[j >> 5] = m;
        __syncthreads();
        m = fmaxf(fmaxf(wred[0], wred[1]), fmaxf(wred[2], wred[3]));
        const float e = expf(t - m);
        float ssum = e;
#pragma unroll
        for (int o = 16; o; o >>= 1)
            ssum += __shfl_xor_sync(0xffffffffu, ssum, o);
        __syncthreads();   // everyone done reading wred (max phase)
        if ((j & 31) == 0) wred[j >> 5] = ssum;
        __syncthreads();
        ssum = wred[0] + wred[1] + wred[2] + wred[3];
        const float s = e / ssum;

        // y2[j] = y1[j]*s[j] + sum_k y1[k]*A2[k,j]   (sy1 valid: synced above)
        float acc2 = 0.f;
#pragma unroll 8
        for (int k = 0; k < HIDE_; k++)
            acc2 = fmaf(sy1[k], A2[k * HIDE_ + j], acc2);
        const float y2 = y1 * s + acc2;
        const float y3 = fmaxf(0.f, W3 * y2);
        sy3[j] = y3;
        __syncthreads();

        // gate[b,c] = sigmoid(sum_k y3[k]*w4[c,k]); thread j covers c=j, c=j+128
#pragma unroll
        for (int cc = 0; cc < 2; cc++) {
            const int c = j + cc * 128;
            const float* __restrict__ w4r = w4 + c * HIDE_;
            float a = 0.f;
#pragma unroll 8
            for (int k = 0; k < HIDE_; k++) a = fmaf(sy3[k], w4r[k], a);
            g_gate[b * C_ + c] = 1.f / (1.f + expf(-a));
        }
        __syncthreads();   // protect sy0/sy1/sy3 before next batch iteration
    }
}

// ---------------------------------------------------------------------------
// Kernel 3: out = x * gate[plane]. One CTA per plane, float4 streaming.
// ---------------------------------------------------------------------------
__global__ __launch_bounds__(256) void k_scale(const float* __restrict__ x,
                                               float* __restrict__ out) {
    const int plane = blockIdx.x;
    const float g = g_gate[plane];
    const float4* __restrict__ p =
        reinterpret_cast<const float4*>(x + (size_t)plane * HW_);
    float4* __restrict__ q =
        reinterpret_cast<float4*>(out + (size_t)plane * HW_);

#pragma unroll 4
    for (int i = threadIdx.x; i < HW4_; i += 256) {
        float4 v = p[i];
        v.x *= g; v.y *= g; v.z *= g; v.w *= g;
        q[i] = v;
    }
}

// ---------------------------------------------------------------------------
extern "C" void kernel_launch(void* const* d_in, const int* in_sizes, int n_in,
                              void* d_out, int out_size) {
    const float* x  = (const float*)d_in[0];
    const float* w1 = (const float*)d_in[1];
    const float* w2 = (const float*)d_in[2];
    const float* w3 = (const float*)d_in[3];
    const float* w4 = (const float*)d_in[4];
    const float* A2 = (const float*)d_in[5];
    float* out = (float*)d_out;

    k_reduce<<<PLANES_, 256>>>(x);
    k_gate<<<1, 128>>>(w1, w2, w3, w4, A2);
    k_scale<<<PLANES_, 256>>>(x, out);
}

// round 4
// speedup vs baseline: 5.6466x; 5.6466x over previous
#include <cuda_runtime.h>
#include <cuda_bf16.h>

// Problem constants
#define B_  16
#define C_  256
#define HIDE_ 128
#define HW_ 16384          // 128*128 elements per (b,c) plane
#define HW4_ 4096          // HW_/4 float4 per plane
#define PLANES_ (B_*C_)    // 4096

// Scratch (no cudaMalloc allowed) — tiny
__device__ float g_y0[PLANES_];    // pooled means (B, C)
__device__ float g_gate[PLANES_];  // sigmoid gate (B, C)

// ---------------------------------------------------------------------------
// Kernel 1: global average pool. One CTA per (b,c) plane, 256 threads,
// float4 vectorized, warp shuffle + smem block reduce.  (82% DRAM — keep.)
// ---------------------------------------------------------------------------
__global__ __launch_bounds__(256) void k_reduce(const float* __restrict__ x) {
    const int plane = blockIdx.x;
    const float4* __restrict__ p =
        reinterpret_cast<const float4*>(x + (size_t)plane * HW_);

    float sum = 0.f;
#pragma unroll 4
    for (int i = threadIdx.x; i < HW4_; i += 256) {
        float4 v = p[i];
        sum += (v.x + v.y) + (v.z + v.w);
    }
#pragma unroll
    for (int o = 16; o; o >>= 1)
        sum += __shfl_xor_sync(0xffffffffu, sum, o);

    __shared__ float wsum[8];
    if ((threadIdx.x & 31) == 0) wsum[threadIdx.x >> 5] = sum;
    __syncthreads();
    if (threadIdx.x == 0) {
        float t = 0.f;
#pragma unroll
        for (int i = 0; i < 8; i++) t += wsum[i];
        g_y0[plane] = t * (1.f / (float)HW_);
    }
}

// ---------------------------------------------------------------------------
// Kernel 2: MLP chain, ONE CTA PER BATCH (grid=16), 128 threads = HIDE lanes.
// float4-vectorized GEMV rows + independent accumulators for ILP.
//   y1 = y0 @ w1^T ; s = softmax(w2*y1) ; y2 = y1*s + y1@A2
//   y3 = relu(w3*y2) ; gate = sigmoid(y3 @ w4^T)
// ---------------------------------------------------------------------------
__global__ __launch_bounds__(128) void k_gate(const float* __restrict__ w1,
                                              const float* __restrict__ w2,
                                              const float* __restrict__ w3,
                                              const float* __restrict__ w4,
                                              const float* __restrict__ A2) {
    __shared__ __align__(16) float sy0[C_];
    __shared__ __align__(16) float sy1[HIDE_];
    __shared__ __align__(16) float sy3[HIDE_];
    __shared__ float wred[4];

    const int b = blockIdx.x;             // one CTA per batch
    const int j = threadIdx.x;            // 0..127 : HIDE lane
    const float W2 = w2[0];
    const float W3 = w3[0];

    // load pooled vector for this batch
    sy0[j]       = g_y0[b * C_ + j];
    sy0[j + 128] = g_y0[b * C_ + 128 + j];
    __syncthreads();

    // y1[j] = sum_c y0[c] * w1[j,c]  — float4, 4 accumulators
    const float4* __restrict__ w1r = reinterpret_cast<const float4*>(w1 + j * C_);
    const float4* __restrict__ sy0v = reinterpret_cast<const float4*>(sy0);
    float a0 = 0.f, a1 = 0.f, a2 = 0.f, a3 = 0.f;
#pragma unroll
    for (int c = 0; c < C_ / 4; c += 4) {
        float4 wa = w1r[c + 0], xa = sy0v[c + 0];
        float4 wb = w1r[c + 1], xb = sy0v[c + 1];
        float4 wc = w1r[c + 2], xc = sy0v[c + 2];
        float4 wd = w1r[c + 3], xd = sy0v[c + 3];
        a0 = fmaf(wa.x, xa.x, fmaf(wa.y, xa.y, fmaf(wa.z, xa.z, fmaf(wa.w, xa.w, a0))));
        a1 = fmaf(wb.x, xb.x, fmaf(wb.y, xb.y, fmaf(wb.z, xb.z, fmaf(wb.w, xb.w, a1))));
        a2 = fmaf(wc.x, xc.x, fmaf(wc.y, xc.y, fmaf(wc.z, xc.z, fmaf(wc.w, xc.w, a2))));
        a3 = fmaf(wd.x, xd.x, fmaf(wd.y, xd.y, fmaf(wd.z, xd.z, fmaf(wd.w, xd.w, a3))));
    }
    const float y1 = (a0 + a1) + (a2 + a3);
    sy1[j] = y1;

    // softmax over 128 lanes of w2*y1
    const float t = W2 * y1;
    float m = t;
#pragma unroll
    for (int o = 16; o; o >>= 1)
        m = fmaxf(m, __shfl_xor_sync(0xffffffffu, m, o));
    if ((j & 31) == 0) wred[j >> 5] = m;
    __syncthreads();
    m = fmaxf(fmaxf(wred[0], wred[1]), fmaxf(wred[2], wred[3]));
    const float e = expf(t - m);
    float ssum = e;
#pragma unroll
    for (int o = 16; o; o >>= 1)
        ssum += __shfl_xor_sync(0xffffffffu, ssum, o);
    __syncthreads();               // all done reading wred (max phase)
    if ((j & 31) == 0) wred[j >> 5] = ssum;
    __syncthreads();
    ssum = wred[0] + wred[1] + wred[2] + wred[3];
    const float s = e / ssum;

    // y2[j] = y1[j]*s[j] + sum_k y1[k]*A2[k,j]  (coalesced column access)
    float b0 = 0.f, b1 = 0.f, b2 = 0.f, b3 = 0.f;
#pragma unroll
    for (int k = 0; k < HIDE_; k += 4) {
        b0 = fmaf(sy1[k + 0], A2[(k + 0) * HIDE_ + j], b0);
        b1 = fmaf(sy1[k + 1], A2[(k + 1) * HIDE_ + j], b1);
        b2 = fmaf(sy1[k + 2], A2[(k + 2) * HIDE_ + j], b2);
        b3 = fmaf(sy1[k + 3], A2[(k + 3) * HIDE_ + j], b3);
    }
    const float y2 = y1 * s + ((b0 + b1) + (b2 + b3));
    const float y3 = fmaxf(0.f, W3 * y2);
    sy3[j] = y3;
    __syncthreads();

    // gate[b,c] = sigmoid(sum_k y3[k]*w4[c,k]); thread j covers c=j, c=j+128
    const float4* __restrict__ sy3v = reinterpret_cast<const float4*>(sy3);
#pragma unroll
    for (int cc = 0; cc < 2; cc++) {
        const int c = j + cc * 128;
        const float4* __restrict__ w4r =
            reinterpret_cast<const float4*>(w4 + c * HIDE_);
        float c0 = 0.f, c1 = 0.f;
#pragma unroll
        for (int k = 0; k < HIDE_ / 4; k += 2) {
            float4 wa = w4r[k + 0], xa = sy3v[k + 0];
            float4 wb = w4r[k + 1], xb = sy3v[k + 1];
            c0 = fmaf(wa.x, xa.x, fmaf(wa.y, xa.y, fmaf(wa.z, xa.z, fmaf(wa.w, xa.w, c0))));
            c1 = fmaf(wb.x, xb.x, fmaf(wb.y, xb.y, fmaf(wb.z, xb.z, fmaf(wb.w, xb.w, c1))));
        }
        const float acc = c0 + c1;
        g_gate[b * C_ + c] = 1.f / (1.f + expf(-acc));
    }
}

// ---------------------------------------------------------------------------
// Kernel 3: out = x * gate[plane]. One CTA per plane, float4 streaming.
// ---------------------------------------------------------------------------
__global__ __launch_bounds__(256) void k_scale(const float* __restrict__ x,
                                               float* __restrict__ out) {
    const int plane = blockIdx.x;
    const float g = g_gate[plane];
    const float4* __restrict__ p =
        reinterpret_cast<const float4*>(x + (size_t)plane * HW_);
    float4* __restrict__ q =
        reinterpret_cast<float4*>(out + (size_t)plane * HW_);

#pragma unroll 4
    for (int i = threadIdx.x; i < HW4_; i += 256) {
        float4 v = p[i];
        v.x *= g; v.y *= g; v.z *= g; v.w *= g;
        q[i] = v;
    }
}

// ---------------------------------------------------------------------------
extern "C" void kernel_launch(void* const* d_in, const int* in_sizes, int n_in,
                              void* d_out, int out_size) {
    const float* x  = (const float*)d_in[0];
    const float* w1 = (const float*)d_in[1];
    const float* w2 = (const float*)d_in[2];
    const float* w3 = (const float*)d_in[3];
    const float* w4 = (const float*)d_in[4];
    const float* A2 = (const float*)d_in[5];
    float* out = (float*)d_out;

    k_reduce<<<PLANES_, 256>>>(x);
    k_gate<<<B_, 128>>>(w1, w2, w3, w4, A2);
    k_scale<<<PLANES_, 256>>>(x, out);
}

// round 6
// speedup vs baseline: 5.9058x; 1.0459x over previous
#include <cuda_runtime.h>
#include <cuda_bf16.h>

// Problem constants
#define B_  16
#define C_  256
#define HIDE_ 128
#define HW_ 16384          // 128*128 elements per (b,c) plane
#define HW4_ 4096          // HW_/4 float4 per plane
#define PLANES_ (B_*C_)    // 4096

// Scratch (no cudaMalloc allowed) — tiny
__device__ float g_y0[PLANES_];    // pooled means (B, C)
__device__ float g_gate[PLANES_];  // sigmoid gate (B, C)

// ---------------------------------------------------------------------------
// Kernel 1: global average pool. One CTA per (b,c) plane, 256 threads,
// float4 vectorized, warp shuffle + smem block reduce. (~81% DRAM, keep.)
// Planes read in ASCENDING order -> tail of x stays hot in L2 for k_scale.
// ---------------------------------------------------------------------------
__global__ __launch_bounds__(256) void k_reduce(const float* __restrict__ x) {
    const int plane = blockIdx.x;
    const float4* __restrict__ p =
        reinterpret_cast<const float4*>(x + (size_t)plane * HW_);

    float sum = 0.f;
#pragma unroll 4
    for (int i = threadIdx.x; i < HW4_; i += 256) {
        float4 v = p[i];
        sum += (v.x + v.y) + (v.z + v.w);
    }
#pragma unroll
    for (int o = 16; o; o >>= 1)
        sum += __shfl_xor_sync(0xffffffffu, sum, o);

    __shared__ float wsum[8];
    if ((threadIdx.x & 31) == 0) wsum[threadIdx.x >> 5] = sum;
    __syncthreads();
    if (threadIdx.x == 0) {
        float t = 0.f;
#pragma unroll
        for (int i = 0; i < 8; i++) t += wsum[i];
        g_y0[plane] = t * (1.f / (float)HW_);
    }
}

// ---------------------------------------------------------------------------
// Kernel 2: MLP chain, one CTA per batch (grid=16), 128 threads = HIDE lanes.
// ---------------------------------------------------------------------------
__global__ __launch_bounds__(128) void k_gate(const float* __restrict__ w1,
                                              const float* __restrict__ w2,
                                              const float* __restrict__ w3,
                                              const float* __restrict__ w4,
                                              const float* __restrict__ A2) {
    __shared__ __align__(16) float sy0[C_];
    __shared__ __align__(16) float sy1[HIDE_];
    __shared__ __align__(16) float sy3[HIDE_];
    __shared__ float wred[4];

    const int b = blockIdx.x;             // one CTA per batch
    const int j = threadIdx.x;            // 0..127 : HIDE lane
    const float W2 = w2[0];
    const float W3 = w3[0];

    sy0[j]       = g_y0[b * C_ + j];
    sy0[j + 128] = g_y0[b * C_ + 128 + j];
    __syncthreads();

    // y1[j] = sum_c y0[c] * w1[j,c]  — float4, 4 accumulators
    const float4* __restrict__ w1r = reinterpret_cast<const float4*>(w1 + j * C_);
    const float4* __restrict__ sy0v = reinterpret_cast<const float4*>(sy0);
    float a0 = 0.f, a1 = 0.f, a2 = 0.f, a3 = 0.f;
#pragma unroll
    for (int c = 0; c < C_ / 4; c += 4) {
        float4 wa = w1r[c + 0], xa = sy0v[c + 0];
        float4 wb = w1r[c + 1], xb = sy0v[c + 1];
        float4 wc = w1r[c + 2], xc = sy0v[c + 2];
        float4 wd = w1r[c + 3], xd = sy0v[c + 3];
        a0 = fmaf(wa.x, xa.x, fmaf(wa.y, xa.y, fmaf(wa.z, xa.z, fmaf(wa.w, xa.w, a0))));
        a1 = fmaf(wb.x, xb.x, fmaf(wb.y, xb.y, fmaf(wb.z, xb.z, fmaf(wb.w, xb.w, a1))));
        a2 = fmaf(wc.x, xc.x, fmaf(wc.y, xc.y, fmaf(wc.z, xc.z, fmaf(wc.w, xc.w, a2))));
        a3 = fmaf(wd.x, xd.x, fmaf(wd.y, xd.y, fmaf(wd.z, xd.z, fmaf(wd.w, xd.w, a3))));
    }
    const float y1 = (a0 + a1) + (a2 + a3);
    sy1[j] = y1;

    // softmax over 128 lanes of w2*y1
    const float t = W2 * y1;
    float m = t;
#pragma unroll
    for (int o = 16; o; o >>= 1)
        m = fmaxf(m, __shfl_xor_sync(0xffffffffu, m, o));
    if ((j & 31) == 0) wred[j >> 5] = m;
    __syncthreads();
    m = fmaxf(fmaxf(wred[0], wred[1]), fmaxf(wred[2], wred[3]));
    const float e = expf(t - m);
    float ssum = e;
#pragma unroll
    for (int o = 16; o; o >>= 1)
        ssum += __shfl_xor_sync(0xffffffffu, ssum, o);
    __syncthreads();               // all done reading wred (max phase)
    if ((j & 31) == 0) wred[j >> 5] = ssum;
    __syncthreads();
    ssum = wred[0] + wred[1] + wred[2] + wred[3];
    const float s = e / ssum;

    // y2[j] = y1[j]*s[j] + sum_k y1[k]*A2[k,j]  (coalesced column access)
    float b0 = 0.f, b1 = 0.f, b2 = 0.f, b3 = 0.f;
#pragma unroll
    for (int k = 0; k < HIDE_; k += 4) {
        b0 = fmaf(sy1[k + 0], A2[(k + 0) * HIDE_ + j], b0);
        b1 = fmaf(sy1[k + 1], A2[(k + 1) * HIDE_ + j], b1);
        b2 = fmaf(sy1[k + 2], A2[(k + 2) * HIDE_ + j], b2);
        b3 = fmaf(sy1[k + 3], A2[(k + 3) * HIDE_ + j], b3);
    }
    const float y2 = y1 * s + ((b0 + b1) + (b2 + b3));
    const float y3 = fmaxf(0.f, W3 * y2);
    sy3[j] = y3;
    __syncthreads();

    // gate[b,c] = sigmoid(sum_k y3[k]*w4[c,k]); thread j covers c=j, c=j+128
    const float4* __restrict__ sy3v = reinterpret_cast<const float4*>(sy3);
#pragma unroll
    for (int cc = 0; cc < 2; cc++) {
        const int c = j + cc * 128;
        const float4* __restrict__ w4r =
            reinterpret_cast<const float4*>(w4 + c * HIDE_);
        float c0 = 0.f, c1 = 0.f;
#pragma unroll
        for (int k = 0; k < HIDE_ / 4; k += 2) {
            float4 wa = w4r[k + 0], xa = sy3v[k + 0];
            float4 wb = w4r[k + 1], xb = sy3v[k + 1];
            c0 = fmaf(wa.x, xa.x, fmaf(wa.y, xa.y, fmaf(wa.z, xa.z, fmaf(wa.w, xa.w, c0))));
            c1 = fmaf(wb.x, xb.x, fmaf(wb.y, xb.y, fmaf(wb.z, xb.z, fmaf(wb.w, xb.w, c1))));
        }
        const float acc = c0 + c1;
        g_gate[b * C_ + c] = 1.f / (1.f + expf(-acc));
    }
}

// ---------------------------------------------------------------------------
// Kernel 3: out = x * gate[plane]. One CTA per plane, float4 streaming.
// REVERSED plane order: the last planes k_reduce touched are still L2-hot,
// so the first wave of k_scale CTAs reads them from L2 instead of DRAM.
// Output stored with __stcs (evict-first) so the 256MB write stream doesn't
// evict the x tail we're reusing.
// ---------------------------------------------------------------------------
__global__ __launch_bounds__(256) void k_scale(const float* __restrict__ x,
                                               float* __restrict__ out) {
    const int plane = (PLANES_ - 1) - blockIdx.x;
    const float g = g_gate[plane];
    const float4* __restrict__ p =
        reinterpret_cast<const float4*>(x + (size_t)plane * HW_);
    float4* __restrict__ q =
        reinterpret_cast<float4*>(out + (size_t)plane * HW_);

#pragma unroll 4
    for (int i = threadIdx.x; i < HW4_; i += 256) {
        float4 v = p[i];
        v.x *= g; v.y *= g; v.z *= g; v.w *= g;
        __stcs(q + i, v);
    }
}

// ---------------------------------------------------------------------------
extern "C" void kernel_launch(void* const* d_in, const int* in_sizes, int n_in,
                              void* d_out, int out_size) {
    const float* x  = (const float*)d_in[0];
    const float* w1 = (const float*)d_in[1];
    const float* w2 = (const float*)d_in[2];
    const float* w3 = (const float*)d_in[3];
    const float* w4 = (const float*)d_in[4];
    const float* A2 = (const float*)d_in[5];
    float* out = (float*)d_out;

    k_reduce<<<PLANES_, 256>>>(x);
    k_gate<<<B_, 128>>>(w1, w2, w3, w4, A2);
    k_scale<<<PLANES_, 256>>>(x, out);
}